// round 6
// baseline (speedup 1.0000x reference)
#include <cuda_runtime.h>
#include <cuda_fp16.h>

#define N_NODES 50000
#define N_EDGES 1600000
#define E_TOT   (N_EDGES + N_NODES)
#define HID 64
#define NBLK 592                 // 4 blocks/SM x 148 SMs: exactly one wave, co-resident
#define NTHR 256
#define NTOT (NBLK * NTHR)
#define NWARPS (NTOT / 32)
#define SCAN_CHUNK 256
#define N_SBLKS ((N_NODES + SCAN_CHUNK - 1) / SCAN_CHUNK)   // 196
#define N_TILES ((N_NODES + 63) / 64)                       // 782

// ---------------- scratch (static __device__: no allocation allowed) ----------------
__device__ int      g_is64;
__device__ int      g_deg[N_NODES];
__device__ float    g_dis[N_NODES];
__device__ int      g_offs[N_NODES + 1];
__device__ int      g_cursor[N_NODES];
__device__ int      g_csr[E_TOT];
__device__ int      g_blkoff[N_SBLKS];
__device__ __half2  g_ts[N_NODES * 32];   // fp16 dis-scaled transformed features
__device__ float    g_h [N_NODES * HID];  // layer-1 hidden (fp32)
__device__ unsigned g_bar_count;          // zero-init; returns to 0 after each barrier
__device__ unsigned g_bar_gen;            // monotonically increasing generation

// ---------------- software grid barrier (all NBLK blocks co-resident) ----------------
__device__ __forceinline__ void grid_sync() {
    __syncthreads();
    if (threadIdx.x == 0) {
        unsigned mygen = *(volatile unsigned*)&g_bar_gen;
        __threadfence();                              // publish this block's writes
        unsigned ticket = atomicAdd(&g_bar_count, 1);
        if (ticket == NBLK - 1) {
            g_bar_count = 0;
            __threadfence();
            atomicAdd(&g_bar_gen, 1);
        } else {
            while (*(volatile unsigned*)&g_bar_gen == mygen) __nanosleep(64);
        }
        __threadfence();                              // acquire others' writes
    }
    __syncthreads();
}

// ---------------- shared memory (20KB union across phases) ----------------
struct SmemT { float4 ws4[64 * 16]; float xs[64 * 64]; };  // transform: 4KB + 16KB
struct SmemA { float wfc[64 * 10]; float bfc[10]; };       // agg-FC
struct SmemS { int wsum[NTHR / 32]; int arr[256]; };       // scans
union SmemU { SmemT t; SmemA a; SmemS s; };

// ---------------- phase helpers ----------------
__device__ __forceinline__ int load_ei(const void* ei, long long flat, int is64) {
    if (is64) return (int)((const long long*)ei)[flat];
    return ((const int*)ei)[flat];
}

// transform a 64-row tile: TS[row] = fp16(dis[row] * (X[row] @ W)); W already in sm.ws4
template <bool USE_H>
__device__ __forceinline__ void transform_tile(SmemT& sm, const float* __restrict__ X,
                                               int row0, int tid) {
    // stage 64x64 X tile
    for (int i = tid; i < 64 * 16; i += NTHR) {
        int r = i >> 4, c4 = i & 15;
        int row = row0 + r;
        float4 v = make_float4(0.f, 0.f, 0.f, 0.f);
        if (row < N_NODES) {
            if (USE_H) v = __ldcg((const float4*)g_h + row * 16 + c4);  // L2: written this launch
            else       v = ((const float4*)X)[row * 16 + c4];
        }
        ((float4*)sm.xs)[r * 16 + c4] = v;
    }
    __syncthreads();

    int tc = tid & 15, tr = tid >> 4;
    float acc[4][4];
#pragma unroll
    for (int a = 0; a < 4; a++)
#pragma unroll
        for (int b = 0; b < 4; b++) acc[a][b] = 0.f;

#pragma unroll 4
    for (int k = 0; k < 64; k++) {
        float4 wv = sm.ws4[k * 16 + tc];
        float x0 = sm.xs[(4 * tr + 0) * 64 + k];
        float x1 = sm.xs[(4 * tr + 1) * 64 + k];
        float x2 = sm.xs[(4 * tr + 2) * 64 + k];
        float x3 = sm.xs[(4 * tr + 3) * 64 + k];
        acc[0][0] = fmaf(x0, wv.x, acc[0][0]); acc[0][1] = fmaf(x0, wv.y, acc[0][1]);
        acc[0][2] = fmaf(x0, wv.z, acc[0][2]); acc[0][3] = fmaf(x0, wv.w, acc[0][3]);
        acc[1][0] = fmaf(x1, wv.x, acc[1][0]); acc[1][1] = fmaf(x1, wv.y, acc[1][1]);
        acc[1][2] = fmaf(x1, wv.z, acc[1][2]); acc[1][3] = fmaf(x1, wv.w, acc[1][3]);
        acc[2][0] = fmaf(x2, wv.x, acc[2][0]); acc[2][1] = fmaf(x2, wv.y, acc[2][1]);
        acc[2][2] = fmaf(x2, wv.z, acc[2][2]); acc[2][3] = fmaf(x2, wv.w, acc[2][3]);
        acc[3][0] = fmaf(x3, wv.x, acc[3][0]); acc[3][1] = fmaf(x3, wv.y, acc[3][1]);
        acc[3][2] = fmaf(x3, wv.z, acc[3][2]); acc[3][3] = fmaf(x3, wv.w, acc[3][3]);
    }

#pragma unroll
    for (int jr = 0; jr < 4; jr++) {
        int row = row0 + 4 * tr + jr;
        if (row < N_NODES) {
            float sc = g_dis[row];
            __half2 p0 = __float22half2_rn(make_float2(acc[jr][0] * sc, acc[jr][1] * sc));
            __half2 p1 = __float22half2_rn(make_float2(acc[jr][2] * sc, acc[jr][3] * sc));
            uint2 packed = make_uint2(*(unsigned*)&p0, *(unsigned*)&p1);
            ((uint2*)g_ts)[row * 16 + tc] = packed;
        }
    }
    __syncthreads();   // xs reuse guard for next tile
}

__device__ __forceinline__ float2 ldcg_h2f2(int idx) {
    unsigned u = __ldcg((const unsigned*)g_ts + idx);   // L2-only: g_ts rewritten between layers
    __half2 h = *(__half2*)&u;
    return __half22float2(h);
}

// aggregate for one node (one warp): returns relu(dis*sum + b) pair for this lane
__device__ __forceinline__ void agg_node(int node, int lane, const float* __restrict__ bias,
                                         float& h0, float& h1) {
    int beg = g_offs[node], end = g_offs[node + 1];
    float ax = 0.f, ay = 0.f;
    int j = beg;
    for (; j + 8 <= end; j += 8) {
        int s0 = g_csr[j + 0], s1 = g_csr[j + 1], s2 = g_csr[j + 2], s3 = g_csr[j + 3];
        int s4 = g_csr[j + 4], s5 = g_csr[j + 5], s6 = g_csr[j + 6], s7 = g_csr[j + 7];
        float2 v0 = ldcg_h2f2(s0 * 32 + lane);
        float2 v1 = ldcg_h2f2(s1 * 32 + lane);
        float2 v2 = ldcg_h2f2(s2 * 32 + lane);
        float2 v3 = ldcg_h2f2(s3 * 32 + lane);
        float2 v4 = ldcg_h2f2(s4 * 32 + lane);
        float2 v5 = ldcg_h2f2(s5 * 32 + lane);
        float2 v6 = ldcg_h2f2(s6 * 32 + lane);
        float2 v7 = ldcg_h2f2(s7 * 32 + lane);
        ax += ((v0.x + v1.x) + (v2.x + v3.x)) + ((v4.x + v5.x) + (v6.x + v7.x));
        ay += ((v0.y + v1.y) + (v2.y + v3.y)) + ((v4.y + v5.y) + (v6.y + v7.y));
    }
    for (; j + 2 <= end; j += 2) {
        int s0 = g_csr[j + 0], s1 = g_csr[j + 1];
        float2 v0 = ldcg_h2f2(s0 * 32 + lane);
        float2 v1 = ldcg_h2f2(s1 * 32 + lane);
        ax += v0.x + v1.x;
        ay += v0.y + v1.y;
    }
    if (j < end) {
        float2 v0 = ldcg_h2f2(g_csr[j] * 32 + lane);
        ax += v0.x;
        ay += v0.y;
    }
    float d  = g_dis[node];
    float2 b2 = ((const float2*)bias)[lane];
    h0 = fmaxf(fmaf(d, ax, b2.x), 0.f);
    h1 = fmaxf(fmaf(d, ay, b2.y), 0.f);
}

// ---------------- the megakernel ----------------
__global__ void __launch_bounds__(NTHR, 4)
k_gcn(const float* __restrict__ x, const void* __restrict__ ei,
      const float* __restrict__ W1, const float* __restrict__ b1,
      const float* __restrict__ W2, const float* __restrict__ b2,
      const float* __restrict__ Wfc, const float* __restrict__ bfc,
      float* __restrict__ OUT) {
    __shared__ SmemU sm;
    const int tid  = threadIdx.x;
    const int gtid = blockIdx.x * NTHR + tid;
    const int lane = tid & 31;
    const int wid_in_blk = tid >> 5;
    const int gwarp = gtid >> 5;

    // ---- A: init deg=1 (self-loop) + dtype detect ----
    for (int i = gtid; i < N_NODES; i += NTOT) g_deg[i] = 1;
    if (gtid == 0) {
        const int* w = (const int*)ei;
        int allzero = 1;
        for (int k = 0; k < 64; k++)
            if (w[2 * k + 1] != 0) { allzero = 0; break; }
        g_is64 = allzero;
    }
    grid_sync();

    // ---- B: degree histogram (4 edges/thread, vectorized) ----
    {
        int is64 = g_is64;
        for (int t = gtid; t < N_EDGES / 4; t += NTOT) {
            int d0, d1, d2, d3;
            if (is64) {
                const int4* p = (const int4*)((const long long*)ei + N_EDGES);
                int4 a = p[2 * t], b = p[2 * t + 1];
                d0 = a.x; d1 = a.z; d2 = b.x; d3 = b.z;
            } else {
                const int4* p = (const int4*)((const int*)ei + N_EDGES);
                int4 a = p[t];
                d0 = a.x; d1 = a.y; d2 = a.z; d3 = a.w;
            }
            atomicAdd(&g_deg[d0], 1);
            atomicAdd(&g_deg[d1], 1);
            atomicAdd(&g_deg[d2], 1);
            atomicAdd(&g_deg[d3], 1);
        }
    }
    grid_sync();

    // ---- C1: per-chunk degree sums ----
    if (blockIdx.x < N_SBLKS) {
        int i = blockIdx.x * SCAN_CHUNK + tid;
        int v = (i < N_NODES) ? g_deg[i] : 0;
#pragma unroll
        for (int off = 16; off; off >>= 1) v += __shfl_xor_sync(0xffffffffu, v, off);
        if (lane == 0) sm.s.wsum[wid_in_blk] = v;
        __syncthreads();
        if (tid == 0) {
            int s = 0;
#pragma unroll
            for (int w = 0; w < NTHR / 32; w++) s += sm.s.wsum[w];
            g_blkoff[blockIdx.x] = s;
        }
    }
    grid_sync();

    // ---- C2: exclusive scan of 196 chunk sums (block 0) ----
    if (blockIdx.x == 0) {
        int v = (tid < N_SBLKS) ? g_blkoff[tid] : 0;
        sm.s.arr[tid] = v;
        __syncthreads();
#pragma unroll
        for (int off = 1; off < 256; off <<= 1) {
            int u = (tid >= off) ? sm.s.arr[tid - off] : 0;
            __syncthreads();
            sm.s.arr[tid] += u;
            __syncthreads();
        }
        if (tid < N_SBLKS) g_blkoff[tid] = sm.s.arr[tid] - v;
        if (tid == 0) g_offs[N_NODES] = E_TOT;
    }
    grid_sync();

    // ---- C3: per-chunk exclusive scan + emit offs/dis/cursor/self-loop ----
    if (blockIdx.x < N_SBLKS) {
        int i = blockIdx.x * SCAN_CHUNK + tid;
        int d = (i < N_NODES) ? g_deg[i] : 0;
        int v = d;
#pragma unroll
        for (int off = 1; off < 32; off <<= 1) {
            int n = __shfl_up_sync(0xffffffffu, v, off);
            if (lane >= off) v += n;
        }
        if (lane == 31) sm.s.wsum[wid_in_blk] = v;
        __syncthreads();
        if (wid_in_blk == 0) {
            int w = (lane < NTHR / 32) ? sm.s.wsum[lane] : 0;
#pragma unroll
            for (int off = 1; off < NTHR / 32; off <<= 1) {
                int n = __shfl_up_sync(0xffffffffu, w, off);
                if (lane >= off) w += n;
            }
            if (lane < NTHR / 32) sm.s.wsum[lane] = w;
        }
        __syncthreads();
        int excl = v - d + (wid_in_blk ? sm.s.wsum[wid_in_blk - 1] : 0) + g_blkoff[blockIdx.x];
        if (i < N_NODES) {
            g_offs[i]   = excl;
            g_dis[i]    = rsqrtf((float)d);
            g_cursor[i] = excl + 1;
            g_csr[excl] = i;                  // self-loop first
        }
    }
    grid_sync();

    // ---- D: scatter edges into CSR ----
    {
        int is64 = g_is64;
        for (int t = gtid; t < N_EDGES / 4; t += NTOT) {
            int d0, d1, d2, d3, s0, s1, s2, s3;
            if (is64) {
                const int4* pd = (const int4*)((const long long*)ei + N_EDGES);
                const int4* ps = (const int4*)((const long long*)ei);
                int4 a = pd[2 * t], b = pd[2 * t + 1];
                int4 c = ps[2 * t], e = ps[2 * t + 1];
                d0 = a.x; d1 = a.z; d2 = b.x; d3 = b.z;
                s0 = c.x; s1 = c.z; s2 = e.x; s3 = e.z;
            } else {
                const int4* pd = (const int4*)((const int*)ei + N_EDGES);
                const int4* ps = (const int4*)((const int*)ei);
                int4 a = pd[t], c = ps[t];
                d0 = a.x; d1 = a.y; d2 = a.z; d3 = a.w;
                s0 = c.x; s1 = c.y; s2 = c.z; s3 = c.w;
            }
            g_csr[atomicAdd(&g_cursor[d0], 1)] = s0;
            g_csr[atomicAdd(&g_cursor[d1], 1)] = s1;
            g_csr[atomicAdd(&g_cursor[d2], 1)] = s2;
            g_csr[atomicAdd(&g_cursor[d3], 1)] = s3;
        }
    }
    grid_sync();

    // ---- E: transform layer 1 (x @ W1, scaled by dis, -> fp16 g_ts) ----
    for (int i = tid; i < 64 * 16; i += NTHR) sm.t.ws4[i] = ((const float4*)W1)[i];
    // (first __syncthreads inside transform_tile orders ws4 for all)
    for (int tile = blockIdx.x; tile < N_TILES; tile += NBLK)
        transform_tile<false>(sm.t, x, tile * 64, tid);
    grid_sync();

    // ---- F: aggregate layer 1 -> g_h (fp32) ----
    for (int node = gwarp; node < N_NODES; node += NWARPS) {
        float h0, h1;
        agg_node(node, lane, b1, h0, h1);
        ((float2*)g_h)[node * 32 + lane] = make_float2(h0, h1);
    }
    grid_sync();

    // ---- G: transform layer 2 (g_h @ W2 -> fp16 g_ts) ----
    for (int i = tid; i < 64 * 16; i += NTHR) sm.t.ws4[i] = ((const float4*)W2)[i];
    for (int tile = blockIdx.x; tile < N_TILES; tile += NBLK)
        transform_tile<true>(sm.t, nullptr, tile * 64, tid);
    grid_sync();

    // ---- H: aggregate layer 2 + fused FC (64 -> 10) ----
    for (int i = tid; i < 640; i += NTHR) sm.a.wfc[i] = Wfc[i];
    if (tid < 10) sm.a.bfc[tid] = bfc[tid];
    __syncthreads();
    for (int node = gwarp; node < N_NODES; node += NWARPS) {
        float h0, h1;
        agg_node(node, lane, b2, h0, h1);
        float myout = 0.f;
#pragma unroll
        for (int o = 0; o < 10; o++) {
            float v = h0 * sm.a.wfc[(2 * lane) * 10 + o] + h1 * sm.a.wfc[(2 * lane + 1) * 10 + o];
#pragma unroll
            for (int off = 16; off; off >>= 1) v += __shfl_xor_sync(0xffffffffu, v, off);
            if (lane == o) myout = v;
        }
        if (lane < 10) OUT[node * 10 + lane] = myout + sm.a.bfc[lane];
    }
}

// ---------------- launch: ONE kernel ----------------
extern "C" void kernel_launch(void* const* d_in, const int* in_sizes, int n_in,
                              void* d_out, int out_size) {
    const float* x   = (const float*)d_in[0];
    const void*  ei  = d_in[1];
    const float* W1  = (const float*)d_in[2];
    const float* b1  = (const float*)d_in[3];
    const float* W2  = (const float*)d_in[4];
    const float* b2  = (const float*)d_in[5];
    const float* Wfc = (const float*)d_in[6];
    const float* bfc = (const float*)d_in[7];
    float*       out = (float*)d_out;

    k_gcn<<<NBLK, NTHR>>>(x, ei, W1, b1, W2, b2, Wfc, bfc, out);
}

// round 7
// speedup vs baseline: 1.1873x; 1.1873x over previous
#include <cuda_runtime.h>
#include <cuda_fp16.h>

#define N_NODES 50000
#define N_EDGES 1600000
#define E_TOT   (N_EDGES + N_NODES)
#define HID 64
#define SCAN_BLK 256
#define N_SBLKS ((N_NODES + SCAN_BLK - 1) / SCAN_BLK)   // 196

// ---------------- scratch (static __device__: no allocation allowed) ----------------
__device__ int     g_is64;                // 1 if edge_index is int64, 0 if int32
__device__ int     g_deg[N_NODES];
__device__ float   g_dis[N_NODES];
__device__ int     g_offs[N_NODES + 1];
__device__ int     g_cursor[N_NODES];
__device__ int     g_csr[E_TOT];
__device__ int     g_blkoff[N_SBLKS];     // scanned block offsets
__device__ __half2 g_ts[N_NODES * 32];    // dis-scaled transformed features (fp16, both layers)
__device__ float   g_h [N_NODES * HID];   // layer-1 hidden output (fp32)

// ---------------- init + dtype detection (fused) ----------------
__global__ void k_init(const int* __restrict__ ei_words) {
    int i = blockIdx.x * blockDim.x + threadIdx.x;
    if (i < N_NODES) g_deg[i] = 1;            // self-loop
    if (i == 0) {
        int allzero = 1;
        for (int k = 0; k < 64; k++)
            if (ei_words[2 * k + 1] != 0) { allzero = 0; break; }
        g_is64 = allzero;
    }
}

// ---------------- CSR build: 4 edges per thread, vectorized index loads ----------------
__global__ void k_hist(const void* __restrict__ ei) {
    int t = blockIdx.x * blockDim.x + threadIdx.x;
    if (t >= N_EDGES / 4) return;
    int d0, d1, d2, d3;
    if (g_is64) {
        const int4* p = (const int4*)((const long long*)ei + N_EDGES);
        int4 a = p[2 * t], b = p[2 * t + 1];
        d0 = a.x; d1 = a.z; d2 = b.x; d3 = b.z;
    } else {
        const int4* p = (const int4*)((const int*)ei + N_EDGES);
        int4 a = p[t];
        d0 = a.x; d1 = a.y; d2 = a.z; d3 = a.w;
    }
    atomicAdd(&g_deg[d0], 1);
    atomicAdd(&g_deg[d1], 1);
    atomicAdd(&g_deg[d2], 1);
    atomicAdd(&g_deg[d3], 1);
}

__global__ void __launch_bounds__(SCAN_BLK) k_scan1() {
    __shared__ int wsum[SCAN_BLK / 32];
    int i = blockIdx.x * SCAN_BLK + threadIdx.x;
    int v = (i < N_NODES) ? g_deg[i] : 0;
#pragma unroll
    for (int off = 16; off; off >>= 1) v += __shfl_xor_sync(0xffffffffu, v, off);
    int lane = threadIdx.x & 31, wid = threadIdx.x >> 5;
    if (lane == 0) wsum[wid] = v;
    __syncthreads();
    if (threadIdx.x == 0) {
        int s = 0;
#pragma unroll
        for (int w = 0; w < SCAN_BLK / 32; w++) s += wsum[w];
        g_blkoff[blockIdx.x] = s;
    }
}

__global__ void __launch_bounds__(256) k_scan2() {
    __shared__ int s[256];
    int t = threadIdx.x;
    int v = (t < N_SBLKS) ? g_blkoff[t] : 0;
    s[t] = v;
    __syncthreads();
#pragma unroll
    for (int off = 1; off < 256; off <<= 1) {
        int u = (t >= off) ? s[t - off] : 0;
        __syncthreads();
        s[t] += u;
        __syncthreads();
    }
    if (t < N_SBLKS) g_blkoff[t] = s[t] - v;
    if (t == 0) g_offs[N_NODES] = E_TOT;
}

__global__ void __launch_bounds__(SCAN_BLK) k_scan3() {
    __shared__ int wsum[SCAN_BLK / 32];
    int i = blockIdx.x * SCAN_BLK + threadIdx.x;
    int d = (i < N_NODES) ? g_deg[i] : 0;
    int lane = threadIdx.x & 31, wid = threadIdx.x >> 5;
    int v = d;
#pragma unroll
    for (int off = 1; off < 32; off <<= 1) {
        int n = __shfl_up_sync(0xffffffffu, v, off);
        if (lane >= off) v += n;
    }
    if (lane == 31) wsum[wid] = v;
    __syncthreads();
    if (wid == 0) {
        int w = (lane < SCAN_BLK / 32) ? wsum[lane] : 0;
#pragma unroll
        for (int off = 1; off < SCAN_BLK / 32; off <<= 1) {
            int n = __shfl_up_sync(0xffffffffu, w, off);
            if (lane >= off) w += n;
        }
        if (lane < SCAN_BLK / 32) wsum[lane] = w;
    }
    __syncthreads();
    int excl = v - d + (wid ? wsum[wid - 1] : 0) + g_blkoff[blockIdx.x];
    if (i < N_NODES) {
        g_offs[i]   = excl;
        g_dis[i]    = rsqrtf((float)d);
        g_cursor[i] = excl + 1;
        g_csr[excl] = i;                  // self-loop first
    }
}

__global__ void k_scatter(const void* __restrict__ ei) {
    int t = blockIdx.x * blockDim.x + threadIdx.x;
    if (t >= N_EDGES / 4) return;
    int d0, d1, d2, d3, s0, s1, s2, s3;
    if (g_is64) {
        const int4* pd = (const int4*)((const long long*)ei + N_EDGES);
        const int4* ps = (const int4*)((const long long*)ei);
        int4 a = pd[2 * t], b = pd[2 * t + 1];
        int4 c = ps[2 * t], e = ps[2 * t + 1];
        d0 = a.x; d1 = a.z; d2 = b.x; d3 = b.z;
        s0 = c.x; s1 = c.z; s2 = e.x; s3 = e.z;
    } else {
        const int4* pd = (const int4*)((const int*)ei + N_EDGES);
        const int4* ps = (const int4*)((const int*)ei);
        int4 a = pd[t], c = ps[t];
        d0 = a.x; d1 = a.y; d2 = a.z; d3 = a.w;
        s0 = c.x; s1 = c.y; s2 = c.z; s3 = c.w;
    }
    g_csr[atomicAdd(&g_cursor[d0], 1)] = s0;
    g_csr[atomicAdd(&g_cursor[d1], 1)] = s1;
    g_csr[atomicAdd(&g_cursor[d2], 1)] = s2;
    g_csr[atomicAdd(&g_cursor[d3], 1)] = s3;
}

// ---------------- transform: TS[i] = fp16( dis[i] * (X[i] @ W) ) ----------------
template <bool USE_H>
__global__ void __launch_bounds__(256) k_transform(const float* __restrict__ Xext,
                                                   const float* __restrict__ W) {
    __shared__ float4 ws4[64 * 16];
    __shared__ float  xs [64 * 64];
    const float* X = USE_H ? g_h : Xext;
    int tid  = threadIdx.x;
    int row0 = blockIdx.x * 64;

    for (int i = tid; i < 64 * 16; i += 256) ws4[i] = ((const float4*)W)[i];
    for (int i = tid; i < 64 * 16; i += 256) {
        int r = i >> 4, c4 = i & 15;
        int row = row0 + r;
        float4 v = make_float4(0.f, 0.f, 0.f, 0.f);
        if (row < N_NODES) v = ((const float4*)X)[row * 16 + c4];
        ((float4*)xs)[r * 16 + c4] = v;
    }
    __syncthreads();

    int tc = tid & 15, tr = tid >> 4;
    float acc[4][4];
#pragma unroll
    for (int a = 0; a < 4; a++)
#pragma unroll
        for (int b = 0; b < 4; b++) acc[a][b] = 0.f;

#pragma unroll 4
    for (int k = 0; k < 64; k++) {
        float4 wv = ws4[k * 16 + tc];
        float x0 = xs[(4 * tr + 0) * 64 + k];
        float x1 = xs[(4 * tr + 1) * 64 + k];
        float x2 = xs[(4 * tr + 2) * 64 + k];
        float x3 = xs[(4 * tr + 3) * 64 + k];
        acc[0][0] = fmaf(x0, wv.x, acc[0][0]); acc[0][1] = fmaf(x0, wv.y, acc[0][1]);
        acc[0][2] = fmaf(x0, wv.z, acc[0][2]); acc[0][3] = fmaf(x0, wv.w, acc[0][3]);
        acc[1][0] = fmaf(x1, wv.x, acc[1][0]); acc[1][1] = fmaf(x1, wv.y, acc[1][1]);
        acc[1][2] = fmaf(x1, wv.z, acc[1][2]); acc[1][3] = fmaf(x1, wv.w, acc[1][3]);
        acc[2][0] = fmaf(x2, wv.x, acc[2][0]); acc[2][1] = fmaf(x2, wv.y, acc[2][1]);
        acc[2][2] = fmaf(x2, wv.z, acc[2][2]); acc[2][3] = fmaf(x2, wv.w, acc[2][3]);
        acc[3][0] = fmaf(x3, wv.x, acc[3][0]); acc[3][1] = fmaf(x3, wv.y, acc[3][1]);
        acc[3][2] = fmaf(x3, wv.z, acc[3][2]); acc[3][3] = fmaf(x3, wv.w, acc[3][3]);
    }

#pragma unroll
    for (int jr = 0; jr < 4; jr++) {
        int row = row0 + 4 * tr + jr;
        if (row < N_NODES) {
            float sc = g_dis[row];
            __half2 p0 = __float22half2_rn(make_float2(acc[jr][0] * sc, acc[jr][1] * sc));
            __half2 p1 = __float22half2_rn(make_float2(acc[jr][2] * sc, acc[jr][3] * sc));
            uint2 packed = make_uint2(*(unsigned*)&p0, *(unsigned*)&p1);
            ((uint2*)g_ts)[row * 16 + tc] = packed;
        }
    }
}

// ---------------- aggregate: warp per node, pair-packed LDG.64 gathers ----------------
// Lanes 0-15 cover edge k's 128B row (8B each); lanes 16-31 cover edge k+1's row.
// CSR indices batch-loaded 32 at a time (1 coalesced LDG) and distributed via shfl.
// Each lane accumulates 4 features; shfl_xor(16) merges even/odd-edge halves.
__device__ __forceinline__ void agg_pair(int se, int so, int lane,
                                         float& f0, float& f1, float& f2, float& f3) {
    int row = (lane < 16) ? se : so;
    uint2 u = __ldg((const uint2*)g_ts + row * 16 + (lane & 15));
    float2 a = __half22float2(*(__half2*)&u.x);
    float2 b = __half22float2(*(__half2*)&u.y);
    f0 += a.x; f1 += a.y; f2 += b.x; f3 += b.y;
}

template <bool FUSE_FC>
__global__ void __launch_bounds__(256) k_agg(const float* __restrict__ bias,
                                             const float* __restrict__ WFC,
                                             const float* __restrict__ BFC,
                                             float* __restrict__ OUT) {
    __shared__ float wfc_s[64 * 10];
    __shared__ float bfc_s[10];
    if (FUSE_FC) {
        for (int i = threadIdx.x; i < 640; i += blockDim.x) wfc_s[i] = WFC[i];
        if (threadIdx.x < 10) bfc_s[threadIdx.x] = BFC[threadIdx.x];
        __syncthreads();
    }
    int node = (blockIdx.x * blockDim.x + threadIdx.x) >> 5;
    int lane = threadIdx.x & 31;
    if (node >= N_NODES) return;

    int beg = g_offs[node], end = g_offs[node + 1];
    float f0 = 0.f, f1 = 0.f, f2 = 0.f, f3 = 0.f;

    int j = beg;
    // full 32-edge chunks: fully unrolled, 16 independent LDG.64 in flight
    for (; j + 32 <= end; j += 32) {
        int myidx = g_csr[j + lane];
#pragma unroll
        for (int k = 0; k < 32; k += 2) {
            int se = __shfl_sync(0xffffffffu, myidx, k);
            int so = __shfl_sync(0xffffffffu, myidx, k + 1);
            agg_pair(se, so, lane, f0, f1, f2, f3);
        }
    }
    // tail (< 32 edges)
    int rem = end - j;
    if (rem > 0) {
        int myidx = (lane < rem) ? g_csr[j + lane] : 0;
        int k = 0;
        for (; k + 2 <= rem; k += 2) {
            int se = __shfl_sync(0xffffffffu, myidx, k);
            int so = __shfl_sync(0xffffffffu, myidx, k + 1);
            agg_pair(se, so, lane, f0, f1, f2, f3);
        }
        if (k < rem) {               // one leftover edge: half warp loads it
            int se = __shfl_sync(0xffffffffu, myidx, k);
            if (lane < 16) {
                uint2 u = __ldg((const uint2*)g_ts + se * 16 + lane);
                float2 a = __half22float2(*(__half2*)&u.x);
                float2 b = __half22float2(*(__half2*)&u.y);
                f0 += a.x; f1 += a.y; f2 += b.x; f3 += b.y;
            }
        }
    }
    // merge even/odd halves: after this both half-warps hold identical full sums
    f0 += __shfl_xor_sync(0xffffffffu, f0, 16);
    f1 += __shfl_xor_sync(0xffffffffu, f1, 16);
    f2 += __shfl_xor_sync(0xffffffffu, f2, 16);
    f3 += __shfl_xor_sync(0xffffffffu, f3, 16);

    float dsc = g_dis[node];
    int l16 = lane & 15;                         // feature group: features 4*l16 .. 4*l16+3
    float4 bb = ((const float4*)bias)[l16];
    float h0 = fmaxf(fmaf(dsc, f0, bb.x), 0.f);
    float h1 = fmaxf(fmaf(dsc, f1, bb.y), 0.f);
    float h2 = fmaxf(fmaf(dsc, f2, bb.z), 0.f);
    float h3 = fmaxf(fmaf(dsc, f3, bb.w), 0.f);

    if (!FUSE_FC) {
        if (lane < 16)
            ((float4*)g_h)[node * 16 + lane] = make_float4(h0, h1, h2, h3);
    } else {
        float myout = 0.f;
#pragma unroll
        for (int o = 0; o < 10; o++) {
            float v = h0 * wfc_s[(4 * l16 + 0) * 10 + o]
                    + h1 * wfc_s[(4 * l16 + 1) * 10 + o]
                    + h2 * wfc_s[(4 * l16 + 2) * 10 + o]
                    + h3 * wfc_s[(4 * l16 + 3) * 10 + o];
            // reduce within each 16-lane half (halves hold identical data)
#pragma unroll
            for (int off = 8; off; off >>= 1) v += __shfl_xor_sync(0xffffffffu, v, off);
            if (lane == o) myout = v;
        }
        if (lane < 10) OUT[node * 10 + lane] = myout + bfc_s[lane];
    }
}

// ---------------- launch ----------------
extern "C" void kernel_launch(void* const* d_in, const int* in_sizes, int n_in,
                              void* d_out, int out_size) {
    const float* x   = (const float*)d_in[0];
    const void*  ei  = d_in[1];
    const float* W1  = (const float*)d_in[2];
    const float* b1  = (const float*)d_in[3];
    const float* W2  = (const float*)d_in[4];
    const float* b2  = (const float*)d_in[5];
    const float* Wfc = (const float*)d_in[6];
    const float* bfc = (const float*)d_in[7];
    float*       out = (float*)d_out;

    k_init   <<<(N_NODES + 255) / 256, 256>>>((const int*)ei);
    k_hist   <<<(N_EDGES / 4 + 255) / 256, 256>>>(ei);
    k_scan1  <<<N_SBLKS, SCAN_BLK>>>();
    k_scan2  <<<1, 256>>>();
    k_scan3  <<<N_SBLKS, SCAN_BLK>>>();
    k_scatter<<<(N_EDGES / 4 + 255) / 256, 256>>>(ei);

    int tgrid = (N_NODES + 63) / 64;
    int agrid = (N_NODES * 32 + 255) / 256;

    k_transform<false><<<tgrid, 256>>>(x, W1);
    k_agg<false>      <<<agrid, 256>>>(b1, nullptr, nullptr, nullptr);
    k_transform<true> <<<tgrid, 256>>>(nullptr, W2);
    k_agg<true>       <<<agrid, 256>>>(b2, Wfc, bfc, out);
}